// round 1
// baseline (speedup 1.0000x reference)
#include <cuda_runtime.h>

#define B_   32
#define L_   128
#define T_   127
#define DM_  768
#define NH_  12
#define DH_  64
#define FF_  3072
#define NL_  12
#define K_   9
#define NTOK (B_*L_)

// ---------------- scratch (device globals; no allocation allowed) ----------
__device__ float g_h[NTOK*DM_];
__device__ float g_q[NTOK*DM_];
__device__ float g_k[NTOK*DM_];
__device__ float g_v[NTOK*DM_];
__device__ float g_ctx[NTOK*DM_];
__device__ float g_tmp[NTOK*DM_];
__device__ float g_ffn[NTOK*FF_];
__device__ float g_em[B_*T_*K_];
__device__ float g_llh[B_];

// ---------------- embedding + LayerNorm ----------------
__global__ void embed_ln_kernel(const int* __restrict__ ids, const int* __restrict__ tt,
                                const float* __restrict__ wemb, const float* __restrict__ pemb,
                                const float* __restrict__ temb,
                                const float* __restrict__ g, const float* __restrict__ bta)
{
    __shared__ float red[8];
    int row = blockIdx.x;
    int pos = row & (L_ - 1);
    int tid = threadIdx.x;           // 256 threads, 3 elems each
    int id = ids[row];
    int ty = tt[row];
    float x[3];
    float s = 0.f;
#pragma unroll
    for (int i = 0; i < 3; i++) {
        int d = tid + i * 256;
        x[i] = wemb[id*DM_ + d] + pemb[pos*DM_ + d] + temb[ty*DM_ + d];
        s += x[i];
    }
    for (int o = 16; o; o >>= 1) s += __shfl_xor_sync(0xffffffffu, s, o);
    if ((tid & 31) == 0) red[tid >> 5] = s;
    __syncthreads();
    if (tid < 8) {
        float v = red[tid];
        for (int o = 4; o; o >>= 1) v += __shfl_xor_sync(0xffu, v, o);
        if (tid == 0) red[0] = v;
    }
    __syncthreads();
    float mean = red[0] * (1.f / DM_);
    __syncthreads();
    float vs = 0.f;
#pragma unroll
    for (int i = 0; i < 3; i++) { float d = x[i] - mean; vs += d * d; }
    for (int o = 16; o; o >>= 1) vs += __shfl_xor_sync(0xffffffffu, vs, o);
    if ((tid & 31) == 0) red[tid >> 5] = vs;
    __syncthreads();
    if (tid < 8) {
        float v = red[tid];
        for (int o = 4; o; o >>= 1) v += __shfl_xor_sync(0xffu, v, o);
        if (tid == 0) red[0] = v;
    }
    __syncthreads();
    float inv = rsqrtf(red[0] * (1.f / DM_) + 1e-12f);
#pragma unroll
    for (int i = 0; i < 3; i++) {
        int d = tid + i * 256;
        g_h[row*DM_ + d] = (x[i] - mean) * inv * g[d] + bta[d];
    }
}

// ---------------- h = LN(h + tmp) ----------------
__global__ void add_ln_kernel(const float* __restrict__ g, const float* __restrict__ bta)
{
    __shared__ float red[8];
    int row = blockIdx.x;
    int tid = threadIdx.x;
    float x[3];
    float s = 0.f;
#pragma unroll
    for (int i = 0; i < 3; i++) {
        int d = tid + i * 256;
        x[i] = g_h[row*DM_ + d] + g_tmp[row*DM_ + d];
        s += x[i];
    }
    for (int o = 16; o; o >>= 1) s += __shfl_xor_sync(0xffffffffu, s, o);
    if ((tid & 31) == 0) red[tid >> 5] = s;
    __syncthreads();
    if (tid < 8) {
        float v = red[tid];
        for (int o = 4; o; o >>= 1) v += __shfl_xor_sync(0xffu, v, o);
        if (tid == 0) red[0] = v;
    }
    __syncthreads();
    float mean = red[0] * (1.f / DM_);
    __syncthreads();
    float vs = 0.f;
#pragma unroll
    for (int i = 0; i < 3; i++) { float d = x[i] - mean; vs += d * d; }
    for (int o = 16; o; o >>= 1) vs += __shfl_xor_sync(0xffffffffu, vs, o);
    if ((tid & 31) == 0) red[tid >> 5] = vs;
    __syncthreads();
    if (tid < 8) {
        float v = red[tid];
        for (int o = 4; o; o >>= 1) v += __shfl_xor_sync(0xffu, v, o);
        if (tid == 0) red[0] = v;
    }
    __syncthreads();
    float inv = rsqrtf(red[0] * (1.f / DM_) + 1e-12f);
#pragma unroll
    for (int i = 0; i < 3; i++) {
        int d = tid + i * 256;
        g_h[row*DM_ + d] = (x[i] - mean) * inv * g[d] + bta[d];
    }
}

// ---------------- generic SGEMM: C[N,M] = A[N,K] @ W[K,M] + bias ; act: 0=none 1=gelu
#define BM 64
#define BN 64
#define BK 16
__global__ void gemm_kernel(const float* __restrict__ A, const float* __restrict__ W,
                            const float* __restrict__ bias, float* __restrict__ C,
                            int N, int K, int M, int act)
{
    __shared__ float As[BK][BM + 1];
    __shared__ float Ws[BK][BN];
    int bm = blockIdx.y * BM;
    int bn = blockIdx.x * BN;
    int tid = threadIdx.x;           // 256
    int tx = tid & 15, ty = tid >> 4;
    float acc[4][4];
#pragma unroll
    for (int i = 0; i < 4; i++)
#pragma unroll
        for (int j = 0; j < 4; j++) acc[i][j] = 0.f;

    for (int k0 = 0; k0 < K; k0 += BK) {
#pragma unroll
        for (int ii = 0; ii < 4; ii++) {
            int i = tid + ii * 256;
            int r = i >> 4, kk = i & 15;                 // BK = 16
            As[kk][r] = A[(size_t)(bm + r) * K + k0 + kk];
        }
#pragma unroll
        for (int ii = 0; ii < 4; ii++) {
            int i = tid + ii * 256;
            int kk = i >> 6, c = i & 63;                 // BN = 64
            Ws[kk][c] = W[(size_t)(k0 + kk) * M + bn + c];
        }
        __syncthreads();
#pragma unroll
        for (int kk = 0; kk < BK; kk++) {
            float a[4], w[4];
#pragma unroll
            for (int i = 0; i < 4; i++) a[i] = As[kk][ty * 4 + i];
#pragma unroll
            for (int j = 0; j < 4; j++) w[j] = Ws[kk][tx * 4 + j];
#pragma unroll
            for (int i = 0; i < 4; i++)
#pragma unroll
                for (int j = 0; j < 4; j++) acc[i][j] += a[i] * w[j];
        }
        __syncthreads();
    }
#pragma unroll
    for (int i = 0; i < 4; i++) {
        int row = bm + ty * 4 + i;
#pragma unroll
        for (int j = 0; j < 4; j++) {
            int col = bn + tx * 4 + j;
            float v = acc[i][j] + bias[col];
            if (act == 1) v = v * 0.5f * (1.f + erff(v * 0.70710678118654752f));
            C[(size_t)row * M + col] = v;
        }
    }
}

// ---------------- fused attention: scores + softmax + PV for one (b,h,q) ----
__global__ void attn_kernel(const int* __restrict__ amask)
{
    __shared__ float kv[128 * 65];
    __shared__ float qsh[64];
    __shared__ float p[128];
    __shared__ float redm[4];
    __shared__ float reds[4];
    int qi = blockIdx.x, h = blockIdx.y, b = blockIdx.z;
    int tid = threadIdx.x;           // 128
    int base = (b * L_) * DM_ + h * DH_;
    if (tid < 64) qsh[tid] = g_q[base + qi * DM_ + tid];
    for (int i = tid; i < 128 * 64; i += 128) {
        int r = i >> 6, d = i & 63;
        kv[r * 65 + d] = g_k[base + r * DM_ + d];
    }
    __syncthreads();
    float s = 0.f;
#pragma unroll 16
    for (int d = 0; d < 64; d++) s += qsh[d] * kv[tid * 65 + d];
    s *= 0.125f;
    if (!amask[b * L_ + tid]) s -= 1e9f;
    float m = s;
    for (int o = 16; o; o >>= 1) m = fmaxf(m, __shfl_xor_sync(0xffffffffu, m, o));
    if ((tid & 31) == 0) redm[tid >> 5] = m;
    __syncthreads();
    m = fmaxf(fmaxf(redm[0], redm[1]), fmaxf(redm[2], redm[3]));
    float e = expf(s - m);
    float su = e;
    for (int o = 16; o; o >>= 1) su += __shfl_xor_sync(0xffffffffu, su, o);
    if ((tid & 31) == 0) reds[tid >> 5] = su;
    __syncthreads();
    su = reds[0] + reds[1] + reds[2] + reds[3];
    p[tid] = e / su;
    __syncthreads();
    for (int i = tid; i < 128 * 64; i += 128) {
        int r = i >> 6, d = i & 63;
        kv[r * 65 + d] = g_v[base + r * DM_ + d];
    }
    __syncthreads();
    if (tid < 64) {
        float acc = 0.f;
#pragma unroll 8
        for (int t = 0; t < 128; t++) acc += p[t] * kv[t * 65 + tid];
        g_ctx[base + qi * DM_ + tid] = acc;
    }
}

// ---------------- emissions: em[b,t,:] = x[b,t+1,:] @ head_W + head_b ------
__global__ void head_kernel(const float* __restrict__ hW, const float* __restrict__ hb)
{
    int t = blockIdx.x, b = blockIdx.y;
    int w = threadIdx.x >> 5, lane = threadIdx.x & 31;   // 9 warps
    const float* x = g_h + (size_t)(b * L_ + t + 1) * DM_;
    float s = 0.f;
    for (int d = lane; d < DM_; d += 32) s += x[d] * hW[d * K_ + w];
    for (int o = 16; o; o >>= 1) s += __shfl_xor_sync(0xffffffffu, s, o);
    if (lane == 0) g_em[(size_t)(b * T_ + t) * K_ + w] = s + hb[w];
}

// ---------------- CRF: llh numerator/partition + Viterbi decode ------------
__global__ void crf_kernel(const int* __restrict__ amask, const int* __restrict__ y,
                           const float* __restrict__ cs, const float* __restrict__ ce,
                           const float* __restrict__ ct,
                           float* __restrict__ out, int out_size)
{
    __shared__ int hist[(T_ - 1) * K_];
    if (threadIdx.x != 0) return;
    int b = blockIdx.x;
    const float* em = g_em + (size_t)b * T_ * K_;
    const int* mrow = amask + b * L_ + 1;   // mask[t] = attention_mask[b][t+1]
    const int* yt = y + b * T_;

    // ---- numerator ----
    int tp = yt[0];
    float num = cs[tp] + em[tp];
    int msum = mrow[0] ? 1 : 0;
    for (int t = 1; t < T_; t++) {
        int tg = yt[t];
        if (mrow[t]) { num += ct[tp * K_ + tg] + em[t * K_ + tg]; msum++; }
        tp = tg;
    }
    num += ce[yt[msum - 1]];

    // ---- forward (log partition) ----
    float alpha[K_], nxt[K_];
    for (int k = 0; k < K_; k++) alpha[k] = cs[k] + em[k];
    for (int t = 1; t < T_; t++) {
        if (!mrow[t]) continue;
        for (int k = 0; k < K_; k++) {
            float mx = -1e30f;
            for (int j = 0; j < K_; j++) mx = fmaxf(mx, alpha[j] + ct[j * K_ + k]);
            float su = 0.f;
            for (int j = 0; j < K_; j++) su += expf(alpha[j] + ct[j * K_ + k] - mx);
            nxt[k] = mx + logf(su) + em[t * K_ + k];
        }
        for (int k = 0; k < K_; k++) alpha[k] = nxt[k];
    }
    float zmx = -1e30f;
    for (int k = 0; k < K_; k++) zmx = fmaxf(zmx, alpha[k] + ce[k]);
    float zs = 0.f;
    for (int k = 0; k < K_; k++) zs += expf(alpha[k] + ce[k] - zmx);
    g_llh[b] = num - (zmx + logf(zs));

    // ---- Viterbi ----
    float sc[K_], nv[K_];
    for (int k = 0; k < K_; k++) sc[k] = cs[k] + em[k];
    for (int t = 1; t < T_; t++) {
        for (int k = 0; k < K_; k++) {
            int bj = 0;
            float bv = sc[0] + ct[k];
            for (int j = 1; j < K_; j++) {
                float c = sc[j] + ct[j * K_ + k];
                if (c > bv) { bv = c; bj = j; }
            }
            hist[(t - 1) * K_ + k] = bj;
            nv[k] = bv + em[t * K_ + k];
        }
        if (mrow[t]) for (int k = 0; k < K_; k++) sc[k] = nv[k];
    }
    int last = 0;
    float bvv = sc[0] + ce[0];
    for (int j = 1; j < K_; j++) {
        float c = sc[j] + ce[j];
        if (c > bvv) { bvv = c; last = j; }
    }
    int dec[T_];
    int tag = last;
    for (int i = T_ - 2; i >= 0; i--) {
        dec[i + 1] = tag;
        int prev = hist[i * K_ + tag];
        if (mrow[i + 1]) tag = prev;
    }
    dec[0] = tag;

    // ---- write decoded (layout depends on out_size; see llh_kernel for llh) ----
    if (out_size >= 1 + B_ * T_) {
        for (int t = 0; t < T_; t++) out[1 + b * T_ + t] = (float)dec[t];
    } else if (out_size == B_ * T_) {
        int* oi = (int*)out;
        for (int t = 0; t < T_; t++) oi[b * T_ + t] = dec[t];
    }
}

__global__ void llh_kernel(float* __restrict__ out, int out_size)
{
    int tid = threadIdx.x;   // 32
    float v = (tid < B_) ? g_llh[tid] : 0.f;
    for (int o = 16; o; o >>= 1) v += __shfl_xor_sync(0xffffffffu, v, o);
    if (tid == 0 && out_size != B_ * T_) out[0] = v * (1.f / B_);
    int base = (out_size >= 1 + B_ * T_) ? (1 + B_ * T_)
             : ((out_size == B_ * T_) ? B_ * T_ : 1);
    for (int i = base + tid; i < out_size; i += 32) out[i] = 0.f;
}

// ---------------- launcher ----------------
extern "C" void kernel_launch(void* const* d_in, const int* in_sizes, int n_in,
                              void* d_out, int out_size)
{
    const int*   ids  = (const int*)d_in[0];
    const int*   am   = (const int*)d_in[1];
    const int*   tt   = (const int*)d_in[2];
    const int*   yt   = (const int*)d_in[3];
    const float* wemb = (const float*)d_in[4];
    const float* pemb = (const float*)d_in[5];
    const float* temb = (const float*)d_in[6];
    const float* eg   = (const float*)d_in[7];
    const float* eb   = (const float*)d_in[8];
    const float* Wq   = (const float*)d_in[9];
    const float* bq   = (const float*)d_in[10];
    const float* Wk   = (const float*)d_in[11];
    const float* bk   = (const float*)d_in[12];
    const float* Wv   = (const float*)d_in[13];
    const float* bv   = (const float*)d_in[14];
    const float* Wo   = (const float*)d_in[15];
    const float* bo   = (const float*)d_in[16];
    const float* l1g  = (const float*)d_in[17];
    const float* l1b  = (const float*)d_in[18];
    const float* W1   = (const float*)d_in[19];
    const float* b1   = (const float*)d_in[20];
    const float* W2   = (const float*)d_in[21];
    const float* b2   = (const float*)d_in[22];
    const float* l2g  = (const float*)d_in[23];
    const float* l2b  = (const float*)d_in[24];
    const float* hW   = (const float*)d_in[25];
    const float* hb   = (const float*)d_in[26];
    const float* cs   = (const float*)d_in[27];
    const float* ce   = (const float*)d_in[28];
    const float* ctr  = (const float*)d_in[29];

    static float *p_h = nullptr, *p_q, *p_k, *p_v, *p_ctx, *p_tmp, *p_ffn;
    if (!p_h) {
        cudaGetSymbolAddress((void**)&p_h,   g_h);
        cudaGetSymbolAddress((void**)&p_q,   g_q);
        cudaGetSymbolAddress((void**)&p_k,   g_k);
        cudaGetSymbolAddress((void**)&p_v,   g_v);
        cudaGetSymbolAddress((void**)&p_ctx, g_ctx);
        cudaGetSymbolAddress((void**)&p_tmp, g_tmp);
        cudaGetSymbolAddress((void**)&p_ffn, g_ffn);
    }

    embed_ln_kernel<<<NTOK, 256>>>(ids, tt, wemb, pemb, temb, eg, eb);

    dim3 gSmall(DM_ / BN, NTOK / BM);   // M=768
    dim3 gFF(FF_ / BN, NTOK / BM);      // M=3072

    for (int l = 0; l < NL_; l++) {
        size_t wOff = (size_t)l * DM_ * DM_;
        gemm_kernel<<<gSmall, 256>>>(p_h, Wq + wOff, bq + l * DM_, p_q, NTOK, DM_, DM_, 0);
        gemm_kernel<<<gSmall, 256>>>(p_h, Wk + wOff, bk + l * DM_, p_k, NTOK, DM_, DM_, 0);
        gemm_kernel<<<gSmall, 256>>>(p_h, Wv + wOff, bv + l * DM_, p_v, NTOK, DM_, DM_, 0);
        attn_kernel<<<dim3(L_, NH_, B_), 128>>>(am);
        gemm_kernel<<<gSmall, 256>>>(p_ctx, Wo + wOff, bo + l * DM_, p_tmp, NTOK, DM_, DM_, 0);
        add_ln_kernel<<<NTOK, 256>>>(l1g + l * DM_, l1b + l * DM_);
        gemm_kernel<<<gFF, 256>>>(p_h, W1 + (size_t)l * DM_ * FF_, b1 + l * FF_, p_ffn,
                                  NTOK, DM_, FF_, 1);
        gemm_kernel<<<gSmall, 256>>>(p_ffn, W2 + (size_t)l * FF_ * DM_, b2 + l * DM_, p_tmp,
                                     NTOK, FF_, DM_, 0);
        add_ln_kernel<<<NTOK, 256>>>(l2g + l * DM_, l2b + l * DM_);
    }

    head_kernel<<<dim3(T_, B_), 288>>>(hW, hb);
    crf_kernel<<<B_, 32>>>(am, yt, cs, ce, ctr, (float*)d_out, out_size);
    llh_kernel<<<1, 32>>>((float*)d_out, out_size);
}

// round 2
// speedup vs baseline: 1.7205x; 1.7205x over previous
#include <cuda_runtime.h>

#define B_   32
#define L_   128
#define T_   127
#define DM_  768
#define NH_  12
#define DH_  64
#define FF_  3072
#define NL_  12
#define K_   9
#define NTOK (B_*L_)

// ---------------- scratch (device globals; no allocation allowed) ----------
__device__ float g_h[NTOK*DM_];
__device__ float g_q[NTOK*DM_];
__device__ float g_k[NTOK*DM_];
__device__ float g_v[NTOK*DM_];
__device__ float g_ctx[NTOK*DM_];
__device__ float g_tmp[NTOK*DM_];
__device__ float g_ffn[NTOK*FF_];
__device__ float g_em[B_*T_*K_];
__device__ float g_llh[B_];

// ---------------- embedding + LayerNorm ----------------
__global__ void embed_ln_kernel(const int* __restrict__ ids, const int* __restrict__ tt,
                                const float* __restrict__ wemb, const float* __restrict__ pemb,
                                const float* __restrict__ temb,
                                const float* __restrict__ g, const float* __restrict__ bta)
{
    __shared__ float red[8];
    int row = blockIdx.x;
    int pos = row & (L_ - 1);
    int tid = threadIdx.x;           // 256 threads, 3 elems each
    int id = ids[row];
    int ty = tt[row];
    float x[3];
    float s = 0.f;
#pragma unroll
    for (int i = 0; i < 3; i++) {
        int d = tid + i * 256;
        x[i] = wemb[id*DM_ + d] + pemb[pos*DM_ + d] + temb[ty*DM_ + d];
        s += x[i];
    }
    for (int o = 16; o; o >>= 1) s += __shfl_xor_sync(0xffffffffu, s, o);
    if ((tid & 31) == 0) red[tid >> 5] = s;
    __syncthreads();
    if (tid < 8) {
        float v = red[tid];
        for (int o = 4; o; o >>= 1) v += __shfl_xor_sync(0xffu, v, o);
        if (tid == 0) red[0] = v;
    }
    __syncthreads();
    float mean = red[0] * (1.f / DM_);
    __syncthreads();
    float vs = 0.f;
#pragma unroll
    for (int i = 0; i < 3; i++) { float d = x[i] - mean; vs += d * d; }
    for (int o = 16; o; o >>= 1) vs += __shfl_xor_sync(0xffffffffu, vs, o);
    if ((tid & 31) == 0) red[tid >> 5] = vs;
    __syncthreads();
    if (tid < 8) {
        float v = red[tid];
        for (int o = 4; o; o >>= 1) v += __shfl_xor_sync(0xffu, v, o);
        if (tid == 0) red[0] = v;
    }
    __syncthreads();
    float inv = rsqrtf(red[0] * (1.f / DM_) + 1e-12f);
#pragma unroll
    for (int i = 0; i < 3; i++) {
        int d = tid + i * 256;
        g_h[row*DM_ + d] = (x[i] - mean) * inv * g[d] + bta[d];
    }
}

// ---------------- h = LN(h + tmp) ----------------
__global__ void add_ln_kernel(const float* __restrict__ g, const float* __restrict__ bta)
{
    __shared__ float red[8];
    int row = blockIdx.x;
    int tid = threadIdx.x;
    float x[3];
    float s = 0.f;
#pragma unroll
    for (int i = 0; i < 3; i++) {
        int d = tid + i * 256;
        x[i] = g_h[row*DM_ + d] + g_tmp[row*DM_ + d];
        s += x[i];
    }
    for (int o = 16; o; o >>= 1) s += __shfl_xor_sync(0xffffffffu, s, o);
    if ((tid & 31) == 0) red[tid >> 5] = s;
    __syncthreads();
    if (tid < 8) {
        float v = red[tid];
        for (int o = 4; o; o >>= 1) v += __shfl_xor_sync(0xffu, v, o);
        if (tid == 0) red[0] = v;
    }
    __syncthreads();
    float mean = red[0] * (1.f / DM_);
    __syncthreads();
    float vs = 0.f;
#pragma unroll
    for (int i = 0; i < 3; i++) { float d = x[i] - mean; vs += d * d; }
    for (int o = 16; o; o >>= 1) vs += __shfl_xor_sync(0xffffffffu, vs, o);
    if ((tid & 31) == 0) red[tid >> 5] = vs;
    __syncthreads();
    if (tid < 8) {
        float v = red[tid];
        for (int o = 4; o; o >>= 1) v += __shfl_xor_sync(0xffu, v, o);
        if (tid == 0) red[0] = v;
    }
    __syncthreads();
    float inv = rsqrtf(red[0] * (1.f / DM_) + 1e-12f);
#pragma unroll
    for (int i = 0; i < 3; i++) {
        int d = tid + i * 256;
        g_h[row*DM_ + d] = (x[i] - mean) * inv * g[d] + bta[d];
    }
}

// ---------------- SGEMM: C[4096,M] = A[4096,K] @ W[K,M] + bias ; act 1=gelu
// 128x64 tile, BK=16, 256 threads, 8x4 micro-tile, double-buffered smem.
__global__ __launch_bounds__(256, 2)
void gemm_kernel(const float* __restrict__ A, const float* __restrict__ W,
                 const float* __restrict__ bias, float* __restrict__ C,
                 int K, int M, int act)
{
    __shared__ float As[2][16][128];   // [buf][k][m]
    __shared__ float Ws[2][16][64];    // [buf][k][n]
    int bm = blockIdx.y * 128;
    int bn = blockIdx.x * 64;
    int tid = threadIdx.x;
    int tx = tid & 15;        // n group
    int ty = tid >> 4;        // m group

    int arow = tid >> 1;               // 0..127
    int akc  = (tid & 1) * 8;          // 0 or 8
    const float* Aptr = A + (size_t)(bm + arow) * K + akc;
    int wkr = tid >> 4;                // 0..15
    int wc  = (tid & 15) * 4;          // 0..60
    const float* Wptr = W + (size_t)wkr * M + bn + wc;

    // prologue: load first k-tile
    float4 a0r = *(const float4*)(Aptr);
    float4 a1r = *(const float4*)(Aptr + 4);
    float4 wr  = *(const float4*)(Wptr);
    As[0][akc+0][arow] = a0r.x; As[0][akc+1][arow] = a0r.y;
    As[0][akc+2][arow] = a0r.z; As[0][akc+3][arow] = a0r.w;
    As[0][akc+4][arow] = a1r.x; As[0][akc+5][arow] = a1r.y;
    As[0][akc+6][arow] = a1r.z; As[0][akc+7][arow] = a1r.w;
    *(float4*)&Ws[0][wkr][wc] = wr;
    __syncthreads();

    float acc[8][4];
#pragma unroll
    for (int i = 0; i < 8; i++)
#pragma unroll
        for (int j = 0; j < 4; j++) acc[i][j] = 0.f;

    int nk = K >> 4;
    for (int t = 0; t < nk; t++) {
        int buf = t & 1;
        if (t + 1 < nk) {
            const float* Ap = Aptr + (t + 1) * 16;
            a0r = *(const float4*)(Ap);
            a1r = *(const float4*)(Ap + 4);
            wr  = *(const float4*)(Wptr + (size_t)(t + 1) * 16 * M);
        }
#pragma unroll
        for (int kk = 0; kk < 16; kk++) {
            float4 a0 = *(const float4*)&As[buf][kk][ty * 4];
            float4 a1 = *(const float4*)&As[buf][kk][ty * 4 + 64];
            float4 w  = *(const float4*)&Ws[buf][kk][tx * 4];
            float am[8] = {a0.x, a0.y, a0.z, a0.w, a1.x, a1.y, a1.z, a1.w};
            float wn[4] = {w.x, w.y, w.z, w.w};
#pragma unroll
            for (int i = 0; i < 8; i++)
#pragma unroll
                for (int j = 0; j < 4; j++) acc[i][j] += am[i] * wn[j];
        }
        if (t + 1 < nk) {
            int nb = buf ^ 1;
            As[nb][akc+0][arow] = a0r.x; As[nb][akc+1][arow] = a0r.y;
            As[nb][akc+2][arow] = a0r.z; As[nb][akc+3][arow] = a0r.w;
            As[nb][akc+4][arow] = a1r.x; As[nb][akc+5][arow] = a1r.y;
            As[nb][akc+6][arow] = a1r.z; As[nb][akc+7][arow] = a1r.w;
            *(float4*)&Ws[nb][wkr][wc] = wr;
            __syncthreads();
        }
    }

    float4 bv = *(const float4*)(bias + bn + tx * 4);
    float bn4[4] = {bv.x, bv.y, bv.z, bv.w};
#pragma unroll
    for (int i = 0; i < 8; i++) {
        int row = bm + ((i < 4) ? (ty * 4 + i) : (64 + ty * 4 + i - 4));
        float4 o;
        float v0 = acc[i][0] + bn4[0];
        float v1 = acc[i][1] + bn4[1];
        float v2 = acc[i][2] + bn4[2];
        float v3 = acc[i][3] + bn4[3];
        if (act == 1) {
            v0 = v0 * 0.5f * (1.f + erff(v0 * 0.70710678118654752f));
            v1 = v1 * 0.5f * (1.f + erff(v1 * 0.70710678118654752f));
            v2 = v2 * 0.5f * (1.f + erff(v2 * 0.70710678118654752f));
            v3 = v3 * 0.5f * (1.f + erff(v3 * 0.70710678118654752f));
        }
        o.x = v0; o.y = v1; o.z = v2; o.w = v3;
        *(float4*)&C[(size_t)row * M + bn + tx * 4] = o;
    }
}

// ---------------- fused attention: one block per (head, batch) --------------
// dynamic smem: Ksh[128][65] | Vsh[128][65] | Psh[16][128] | Qsh[8][2][64]
#define KV_PITCH 65
#define ATTN_SMEM_FLOATS (2*128*KV_PITCH + 16*128 + 8*2*64)
__global__ void attn_kernel(const int* __restrict__ amask)
{
    extern __shared__ float sm[];
    float* Ksh = sm;
    float* Vsh = sm + 128 * KV_PITCH;
    float* Psh = sm + 2 * 128 * KV_PITCH;       // [wid*2+qs][128]
    float* Qsh = Psh + 16 * 128;                // [wid][qs][64]

    int h = blockIdx.x, b = blockIdx.y;
    int tid = threadIdx.x;
    int wid = tid >> 5, lane = tid & 31;
    size_t base = (size_t)(b * L_) * DM_ + h * DH_;

    for (int i = tid; i < 128 * 64; i += 256) {
        int r = i >> 6, d = i & 63;
        Ksh[r * KV_PITCH + d] = g_k[base + (size_t)r * DM_ + d];
        Vsh[r * KV_PITCH + d] = g_v[base + (size_t)r * DM_ + d];
    }
    __syncthreads();

    int m0 = amask[b * L_ + lane];
    int m1 = amask[b * L_ + lane + 32];
    int m2 = amask[b * L_ + lane + 64];
    int m3 = amask[b * L_ + lane + 96];

    for (int q0 = wid * 2; q0 < 128; q0 += 16) {
        // stage the two q rows
        const float* qp0 = g_q + base + (size_t)q0 * DM_;
        Qsh[(wid * 2 + 0) * 64 + lane]      = qp0[lane];
        Qsh[(wid * 2 + 0) * 64 + lane + 32] = qp0[lane + 32];
        Qsh[(wid * 2 + 1) * 64 + lane]      = qp0[DM_ + lane];
        Qsh[(wid * 2 + 1) * 64 + lane + 32] = qp0[DM_ + lane + 32];
        __syncwarp();

        float s0[4] = {0.f, 0.f, 0.f, 0.f};
        float s1[4] = {0.f, 0.f, 0.f, 0.f};
#pragma unroll 8
        for (int d = 0; d < 64; d++) {
            float qv0 = Qsh[(wid * 2 + 0) * 64 + d];
            float qv1 = Qsh[(wid * 2 + 1) * 64 + d];
#pragma unroll
            for (int c = 0; c < 4; c++) {
                float kv = Ksh[(lane + c * 32) * KV_PITCH + d];
                s0[c] += qv0 * kv;
                s1[c] += qv1 * kv;
            }
        }
        int mk[4] = {m0, m1, m2, m3};
#pragma unroll
        for (int c = 0; c < 4; c++) {
            s0[c] = s0[c] * 0.125f + (mk[c] ? 0.f : -1e9f);
            s1[c] = s1[c] * 0.125f + (mk[c] ? 0.f : -1e9f);
        }
        // softmax (per query, over 128 scores spread 4/lane)
        float mx0 = fmaxf(fmaxf(s0[0], s0[1]), fmaxf(s0[2], s0[3]));
        float mx1 = fmaxf(fmaxf(s1[0], s1[1]), fmaxf(s1[2], s1[3]));
        for (int o = 16; o; o >>= 1) {
            mx0 = fmaxf(mx0, __shfl_xor_sync(0xffffffffu, mx0, o));
            mx1 = fmaxf(mx1, __shfl_xor_sync(0xffffffffu, mx1, o));
        }
        float e0[4], e1[4];
        float su0 = 0.f, su1 = 0.f;
#pragma unroll
        for (int c = 0; c < 4; c++) {
            e0[c] = expf(s0[c] - mx0); su0 += e0[c];
            e1[c] = expf(s1[c] - mx1); su1 += e1[c];
        }
        for (int o = 16; o; o >>= 1) {
            su0 += __shfl_xor_sync(0xffffffffu, su0, o);
            su1 += __shfl_xor_sync(0xffffffffu, su1, o);
        }
        float r0 = 1.f / su0, r1 = 1.f / su1;
#pragma unroll
        for (int c = 0; c < 4; c++) {
            Psh[(wid * 2 + 0) * 128 + lane + c * 32] = e0[c] * r0;
            Psh[(wid * 2 + 1) * 128 + lane + c * 32] = e1[c] * r1;
        }
        __syncwarp();
        // PV: each lane does d = lane and lane+32 for both queries
        float a00 = 0.f, a01 = 0.f, a10 = 0.f, a11 = 0.f;
#pragma unroll 4
        for (int k = 0; k < 128; k++) {
            float p0 = Psh[(wid * 2 + 0) * 128 + k];
            float p1 = Psh[(wid * 2 + 1) * 128 + k];
            float v0 = Vsh[k * KV_PITCH + lane];
            float v1 = Vsh[k * KV_PITCH + lane + 32];
            a00 += p0 * v0; a01 += p0 * v1;
            a10 += p1 * v0; a11 += p1 * v1;
        }
        g_ctx[base + (size_t)q0 * DM_ + lane]            = a00;
        g_ctx[base + (size_t)q0 * DM_ + lane + 32]       = a01;
        g_ctx[base + (size_t)(q0 + 1) * DM_ + lane]      = a10;
        g_ctx[base + (size_t)(q0 + 1) * DM_ + lane + 32] = a11;
        __syncwarp();
    }
}

// ---------------- emissions: em[b,t,:] = x[b,t+1,:] @ head_W + head_b ------
__global__ void head_kernel(const float* __restrict__ hW, const float* __restrict__ hb)
{
    int t = blockIdx.x, b = blockIdx.y;
    int w = threadIdx.x >> 5, lane = threadIdx.x & 31;   // 9 warps
    const float* x = g_h + (size_t)(b * L_ + t + 1) * DM_;
    float s = 0.f;
    for (int d = lane; d < DM_; d += 32) s += x[d] * hW[d * K_ + w];
    for (int o = 16; o; o >>= 1) s += __shfl_xor_sync(0xffffffffu, s, o);
    if (lane == 0) g_em[(size_t)(b * T_ + t) * K_ + w] = s + hb[w];
}

// ---------------- CRF: llh numerator/partition + Viterbi decode ------------
__global__ void crf_kernel(const int* __restrict__ amask, const int* __restrict__ y,
                           const float* __restrict__ cs, const float* __restrict__ ce,
                           const float* __restrict__ ct,
                           float* __restrict__ out, int out_size)
{
    __shared__ int hist[(T_ - 1) * K_];
    if (threadIdx.x != 0) return;
    int b = blockIdx.x;
    const float* em = g_em + (size_t)b * T_ * K_;
    const int* mrow = amask + b * L_ + 1;   // mask[t] = attention_mask[b][t+1]
    const int* yt = y + b * T_;

    // ---- numerator ----
    int tp = yt[0];
    float num = cs[tp] + em[tp];
    int msum = mrow[0] ? 1 : 0;
    for (int t = 1; t < T_; t++) {
        int tg = yt[t];
        if (mrow[t]) { num += ct[tp * K_ + tg] + em[t * K_ + tg]; msum++; }
        tp = tg;
    }
    num += ce[yt[msum - 1]];

    // ---- forward (log partition) ----
    float alpha[K_], nxt[K_];
    for (int k = 0; k < K_; k++) alpha[k] = cs[k] + em[k];
    for (int t = 1; t < T_; t++) {
        if (!mrow[t]) continue;
        for (int k = 0; k < K_; k++) {
            float mx = -1e30f;
            for (int j = 0; j < K_; j++) mx = fmaxf(mx, alpha[j] + ct[j * K_ + k]);
            float su = 0.f;
            for (int j = 0; j < K_; j++) su += expf(alpha[j] + ct[j * K_ + k] - mx);
            nxt[k] = mx + logf(su) + em[t * K_ + k];
        }
        for (int k = 0; k < K_; k++) alpha[k] = nxt[k];
    }
    float zmx = -1e30f;
    for (int k = 0; k < K_; k++) zmx = fmaxf(zmx, alpha[k] + ce[k]);
    float zs = 0.f;
    for (int k = 0; k < K_; k++) zs += expf(alpha[k] + ce[k] - zmx);
    g_llh[b] = num - (zmx + logf(zs));

    // ---- Viterbi ----
    float sc[K_], nv[K_];
    for (int k = 0; k < K_; k++) sc[k] = cs[k] + em[k];
    for (int t = 1; t < T_; t++) {
        for (int k = 0; k < K_; k++) {
            int bj = 0;
            float bv = sc[0] + ct[k];
            for (int j = 1; j < K_; j++) {
                float c = sc[j] + ct[j * K_ + k];
                if (c > bv) { bv = c; bj = j; }
            }
            hist[(t - 1) * K_ + k] = bj;
            nv[k] = bv + em[t * K_ + k];
        }
        if (mrow[t]) for (int k = 0; k < K_; k++) sc[k] = nv[k];
    }
    int last = 0;
    float bvv = sc[0] + ce[0];
    for (int j = 1; j < K_; j++) {
        float c = sc[j] + ce[j];
        if (c > bvv) { bvv = c; last = j; }
    }
    int dec[T_];
    int tag = last;
    for (int i = T_ - 2; i >= 0; i--) {
        dec[i + 1] = tag;
        int prev = hist[i * K_ + tag];
        if (mrow[i + 1]) tag = prev;
    }
    dec[0] = tag;

    // ---- write decoded (layout depends on out_size; see llh_kernel for llh) ----
    if (out_size >= 1 + B_ * T_) {
        for (int t = 0; t < T_; t++) out[1 + b * T_ + t] = (float)dec[t];
    } else if (out_size == B_ * T_) {
        int* oi = (int*)out;
        for (int t = 0; t < T_; t++) oi[b * T_ + t] = dec[t];
    }
}

__global__ void llh_kernel(float* __restrict__ out, int out_size)
{
    int tid = threadIdx.x;   // 32
    float v = (tid < B_) ? g_llh[tid] : 0.f;
    for (int o = 16; o; o >>= 1) v += __shfl_xor_sync(0xffffffffu, v, o);
    if (tid == 0 && out_size != B_ * T_) out[0] = v * (1.f / B_);
    int base = (out_size >= 1 + B_ * T_) ? (1 + B_ * T_)
             : ((out_size == B_ * T_) ? B_ * T_ : 1);
    for (int i = base + tid; i < out_size; i += 32) out[i] = 0.f;
}

// ---------------- launcher ----------------
extern "C" void kernel_launch(void* const* d_in, const int* in_sizes, int n_in,
                              void* d_out, int out_size)
{
    const int*   ids  = (const int*)d_in[0];
    const int*   am   = (const int*)d_in[1];
    const int*   tt   = (const int*)d_in[2];
    const int*   yt   = (const int*)d_in[3];
    const float* wemb = (const float*)d_in[4];
    const float* pemb = (const float*)d_in[5];
    const float* temb = (const float*)d_in[6];
    const float* eg   = (const float*)d_in[7];
    const float* eb   = (const float*)d_in[8];
    const float* Wq   = (const float*)d_in[9];
    const float* bq   = (const float*)d_in[10];
    const float* Wk   = (const float*)d_in[11];
    const float* bk   = (const float*)d_in[12];
    const float* Wv   = (const float*)d_in[13];
    const float* bv   = (const float*)d_in[14];
    const float* Wo   = (const float*)d_in[15];
    const float* bo   = (const float*)d_in[16];
    const float* l1g  = (const float*)d_in[17];
    const float* l1b  = (const float*)d_in[18];
    const float* W1   = (const float*)d_in[19];
    const float* b1   = (const float*)d_in[20];
    const float* W2   = (const float*)d_in[21];
    const float* b2   = (const float*)d_in[22];
    const float* l2g  = (const float*)d_in[23];
    const float* l2b  = (const float*)d_in[24];
    const float* hW   = (const float*)d_in[25];
    const float* hb   = (const float*)d_in[26];
    const float* cs   = (const float*)d_in[27];
    const float* ce   = (const float*)d_in[28];
    const float* ctr  = (const float*)d_in[29];

    static float *p_h = nullptr, *p_q, *p_k, *p_v, *p_ctx, *p_tmp, *p_ffn;
    if (!p_h) {
        cudaGetSymbolAddress((void**)&p_h,   g_h);
        cudaGetSymbolAddress((void**)&p_q,   g_q);
        cudaGetSymbolAddress((void**)&p_k,   g_k);
        cudaGetSymbolAddress((void**)&p_v,   g_v);
        cudaGetSymbolAddress((void**)&p_ctx, g_ctx);
        cudaGetSymbolAddress((void**)&p_tmp, g_tmp);
        cudaGetSymbolAddress((void**)&p_ffn, g_ffn);
        cudaFuncSetAttribute(attn_kernel, cudaFuncAttributeMaxDynamicSharedMemorySize,
                             ATTN_SMEM_FLOATS * 4);
    }

    embed_ln_kernel<<<NTOK, 256>>>(ids, tt, wemb, pemb, temb, eg, eb);

    dim3 gSmall(DM_ / 64, NTOK / 128);   // M=768 : 12 x 32
    dim3 gFF(FF_ / 64, NTOK / 128);      // M=3072: 48 x 32

    for (int l = 0; l < NL_; l++) {
        size_t wOff = (size_t)l * DM_ * DM_;
        gemm_kernel<<<gSmall, 256>>>(p_h, Wq + wOff, bq + l * DM_, p_q, DM_, DM_, 0);
        gemm_kernel<<<gSmall, 256>>>(p_h, Wk + wOff, bk + l * DM_, p_k, DM_, DM_, 0);
        gemm_kernel<<<gSmall, 256>>>(p_h, Wv + wOff, bv + l * DM_, p_v, DM_, DM_, 0);
        attn_kernel<<<dim3(NH_, B_), 256, ATTN_SMEM_FLOATS * 4>>>(am);
        gemm_kernel<<<gSmall, 256>>>(p_ctx, Wo + wOff, bo + l * DM_, p_tmp, DM_, DM_, 0);
        add_ln_kernel<<<NTOK, 256>>>(l1g + l * DM_, l1b + l * DM_);
        gemm_kernel<<<gFF, 256>>>(p_h, W1 + (size_t)l * DM_ * FF_, b1 + l * FF_, p_ffn,
                                  DM_, FF_, 1);
        gemm_kernel<<<gSmall, 256>>>(p_ffn, W2 + (size_t)l * FF_ * DM_, b2 + l * DM_, p_tmp,
                                     FF_, DM_, 0);
        add_ln_kernel<<<NTOK, 256>>>(l2g + l * DM_, l2b + l * DM_);
    }

    head_kernel<<<dim3(T_, B_), 288>>>(hW, hb);
    crf_kernel<<<B_, 32>>>(am, yt, cs, ce, ctr, (float*)d_out, out_size);
    llh_kernel<<<1, 32>>>((float*)d_out, out_size);
}